// round 9
// baseline (speedup 1.0000x reference)
#include <cuda_runtime.h>

// Problem constants (fixed by reference setup_inputs)
#define C_    128
#define D_    24
#define H_    128
#define W_    128
#define HW_   (H_ * W_)
#define DHW_  (D_ * HW_)
#define OUTH  7
#define OUTD  4
#define SN_   2
#define NBINS (OUTD * OUTH * OUTH)   // 196
#define CG    16                     // channels per block (gridDim.y = 8)
#define NWARP 5
#define TPB   (NWARP * 32)           // 160 threads
#define NCOMBO (OUTD * OUTH)         // 28 (h,d) combos

#define SCALE_XY 0.125f
#define SCALE_Z  0.25f

// 5-warp CTA, 28 (d,h) combos taken interleaved (k = j*5 + wi), so at any
// instant the CTA's warps sit on 5 CONSECUTIVE combos (same/adjacent d,
// contiguous h) — preserves the intra-CTA L2/L1 reuse window (R8 lesson:
// blocked warp-major assignment desynchronizes warps and inflates DRAM 3x).
// RF quantization: 80 regs x 160 threads -> 5 CTAs/SM = 25 warps (vs 21).
__global__ __launch_bounds__(TPB, 5)
void roialign3d_kernel(const float* __restrict__ feat,
                       const float* __restrict__ rois,
                       float* __restrict__ out,
                       int R)
{
    const int r    = blockIdx.x;         // roi
    const int cg   = blockIdx.y;         // channel group
    const int wi   = threadIdx.x >> 5;   // warp id (0..4)
    const int lane = threadIdx.x & 31;
    // lane -> (w bin, x tap). 28 active lanes; lanes 28..31 mirror w=6 (weight 0).
    const int  wbin   = (lane >> 2) < OUTH ? (lane >> 2) : (OUTH - 1);
    const int  tap    = lane & 3;        // (sample = tap>>1, corner = tap&1)
    const bool active = (lane >> 2) < OUTH;

    // ---- ROI params (uniform) ----
    const float* roi = rois + (size_t)r * 7;
    const int   b  = (int)__ldg(roi + 0);
    const float x1 = __ldg(roi + 1) * SCALE_XY;
    const float y1 = __ldg(roi + 2) * SCALE_XY;
    const float x2 = __ldg(roi + 3) * SCALE_XY;
    const float y2 = __ldg(roi + 4) * SCALE_XY;
    const float z1 = __ldg(roi + 5) * SCALE_Z;
    const float z2 = __ldg(roi + 6) * SCALE_Z;

    const float bw = fmaxf(x2 - x1, 1.0f) * (1.0f / OUTH);
    const float bh = fmaxf(y2 - y1, 1.0f) * (1.0f / OUTH);
    const float bd = fmaxf(z2 - z1, 1.0f) * (1.0f / OUTD);

    // ---- This lane's x tap: offset (clipped in-bounds) + weight (validity folded) ----
    int   xoff;
    float xw;
    {
        const int   s  = tap >> 1;
        float c  = x1 + ((float)wbin + 0.25f + 0.5f * (float)s) * bw;
        float v  = (c > -1.0f && c < (float)W_) ? 1.0f : 0.0f;
        float cc = fminf(fmaxf(c, 0.0f), (float)(W_ - 1));
        int   lo = (int)cc;
        int   hi = (lo < W_ - 1) ? lo + 1 : lo;
        float f  = cc - (float)lo;
        xoff = (tap & 1) ? hi : lo;
        xw   = ((tap & 1) ? f : (1.0f - f)) * v;
        if (!active) xw = 0.0f;
    }

    const int c0 = cg * CG;
    const float* pbase = feat + ((size_t)b * C_ + c0) * (size_t)DHW_ + xoff;
    float* obase0 = out + ((size_t)(r * C_ + c0)) * (size_t)NBINS + wbin;

    // ---- Interleaved combo loop: k = wi, wi+5, ... ; k = d*7 + h ----
    for (int k = wi; k < NCOMBO; k += NWARP) {
        const int d = k / OUTH;
        const int h = k % OUTH;

        // 4 y taps (depend on h)
        int   yoff[4];
        float yw[4];
#pragma unroll
        for (int s = 0; s < SN_; s++) {
            float c  = y1 + ((float)h + 0.25f + 0.5f * (float)s) * bh;
            float v  = (c > -1.0f && c < (float)H_) ? 1.0f : 0.0f;
            float cc = fminf(fmaxf(c, 0.0f), (float)(H_ - 1));
            int   lo = (int)cc;
            int   hi = (lo < H_ - 1) ? lo + 1 : lo;
            float f  = cc - (float)lo;
            yoff[2*s]   = lo * W_;  yw[2*s]   = (1.0f - f) * v;
            yoff[2*s+1] = hi * W_;  yw[2*s+1] = f * v;
        }

        // 4 z taps (depend on d)
        int   zoff[4];
        float zw[4];
#pragma unroll
        for (int s = 0; s < SN_; s++) {
            float c  = z1 + ((float)d + 0.25f + 0.5f * (float)s) * bd;
            float v  = (c > -1.0f && c < (float)D_) ? 1.0f : 0.0f;
            float cc = fminf(fmaxf(c, 0.0f), (float)(D_ - 1));
            int   lo = (int)cc;
            int   hi = (lo < D_ - 1) ? lo + 1 : lo;
            float f  = cc - (float)lo;
            zoff[2*s]   = lo * HW_;  zw[2*s]   = (1.0f - f) * v;
            zoff[2*s+1] = hi * HW_;  zw[2*s+1] = f * v;
        }

        // 16 row offsets + scalar weights (uniform across warp)
        int   rowoff[16];
        float wzy[16];
#pragma unroll
        for (int zt = 0; zt < 4; zt++)
#pragma unroll
            for (int yt = 0; yt < 4; yt++) {
                rowoff[zt * 4 + yt] = zoff[zt] + yoff[yt];
                wzy[zt * 4 + yt]    = zw[zt] * yw[yt];
            }

        float* od = obase0 + (size_t)d * (OUTH * OUTH) + h * OUTH;

        // ---- Channel loop, 2 channels at a time (32 independent LDGs) ----
        for (int ci = 0; ci < CG; ci += 2) {
            const float* pA = pbase + (size_t)ci * DHW_;
            const float* pB = pA + DHW_;

            float vA[16], vB[16];
#pragma unroll
            for (int i = 0; i < 16; i++) {
                vA[i] = __ldg(pA + rowoff[i]);
                vB[i] = __ldg(pB + rowoff[i]);
            }

            // two partial chains each to shorten the FMA dependency
            float a0 = 0.f, a1 = 0.f, b0 = 0.f, b1 = 0.f;
#pragma unroll
            for (int i = 0; i < 16; i += 2) {
                a0 = fmaf(wzy[i],     vA[i],     a0);
                a1 = fmaf(wzy[i + 1], vA[i + 1], a1);
                b0 = fmaf(wzy[i],     vB[i],     b0);
                b1 = fmaf(wzy[i + 1], vB[i + 1], b1);
            }
            float accA = (a0 + a1) * xw;
            float accB = (b0 + b1) * xw;

            // reduce across the 4 x-taps (lanes 4w..4w+3)
            accA += __shfl_xor_sync(0xFFFFFFFFu, accA, 1);
            accA += __shfl_xor_sync(0xFFFFFFFFu, accA, 2);
            accB += __shfl_xor_sync(0xFFFFFFFFu, accB, 1);
            accB += __shfl_xor_sync(0xFFFFFFFFu, accB, 2);

            if (active && tap == 0) {
                od[(size_t)ci * NBINS]       = accA * 0.125f;  // mean over 8 samples
                od[(size_t)(ci + 1) * NBINS] = accB * 0.125f;
            }
        }
    }
}

extern "C" void kernel_launch(void* const* d_in, const int* in_sizes, int n_in,
                              void* d_out, int out_size)
{
    const float* feat = (const float*)d_in[0];
    const float* rois = (const float*)d_in[1];
    float* out = (float*)d_out;

    const int R = in_sizes[1] / 7;   // 256

    dim3 grid(R, C_ / CG, 1);        // 256 x 8 = 2048 blocks
    dim3 block(TPB, 1, 1);           // 160 threads (5 warps)
    roialign3d_kernel<<<grid, block>>>(feat, rois, out, R);
}

// round 10
// speedup vs baseline: 1.9691x; 1.9691x over previous
#include <cuda_runtime.h>

// Problem constants (fixed by reference setup_inputs)
#define C_    128
#define D_    24
#define H_    128
#define W_    128
#define HW_   (H_ * W_)
#define DHW_  (D_ * HW_)
#define OUTH  7
#define OUTD  4
#define SN_   2
#define NBINS (OUTD * OUTH * OUTH)   // 196
#define CG    16                     // channels per block (gridDim.y = 8)
#define NWARP 5
#define TPB   (NWARP * 32)           // 160 threads
#define NCOMBO (OUTD * OUTH)         // 28 (h,d) combos

#define SCALE_XY 0.125f
#define SCALE_Z  0.25f

// 5-warp CTA, 28 (d,h) combos taken interleaved (k = j*5 + wi): at any
// instant the CTA's warps sit on 5 CONSECUTIVE combos — preserves the
// intra-CTA L2 reuse window (verified in R9: DRAM stayed low).
// launch_bounds min-blocks = 4 (NOT 5): ceiling 102 regs leaves ptxas
// slack to keep the natural 80-reg allocation with the 32-LDG batch intact
// (R2/R6/R9 law: ceiling pressure near the natural allocation serializes
// the load batch). Residency is then RF-limited: 65536/(80*160) = 5 CTAs
// per SM = 25 warps (vs 21 for 7-warp CTAs).
__global__ __launch_bounds__(TPB, 4)
void roialign3d_kernel(const float* __restrict__ feat,
                       const float* __restrict__ rois,
                       float* __restrict__ out,
                       int R)
{
    const int r    = blockIdx.x;         // roi
    const int cg   = blockIdx.y;         // channel group
    const int wi   = threadIdx.x >> 5;   // warp id (0..4)
    const int lane = threadIdx.x & 31;
    // lane -> (w bin, x tap). 28 active lanes; lanes 28..31 mirror w=6 (weight 0).
    const int  wbin   = (lane >> 2) < OUTH ? (lane >> 2) : (OUTH - 1);
    const int  tap    = lane & 3;        // (sample = tap>>1, corner = tap&1)
    const bool active = (lane >> 2) < OUTH;

    // ---- ROI params (uniform) ----
    const float* roi = rois + (size_t)r * 7;
    const int   b  = (int)__ldg(roi + 0);
    const float x1 = __ldg(roi + 1) * SCALE_XY;
    const float y1 = __ldg(roi + 2) * SCALE_XY;
    const float x2 = __ldg(roi + 3) * SCALE_XY;
    const float y2 = __ldg(roi + 4) * SCALE_XY;
    const float z1 = __ldg(roi + 5) * SCALE_Z;
    const float z2 = __ldg(roi + 6) * SCALE_Z;

    const float bw = fmaxf(x2 - x1, 1.0f) * (1.0f / OUTH);
    const float bh = fmaxf(y2 - y1, 1.0f) * (1.0f / OUTH);
    const float bd = fmaxf(z2 - z1, 1.0f) * (1.0f / OUTD);

    // ---- This lane's x tap: offset (clipped in-bounds) + weight (validity folded) ----
    int   xoff;
    float xw;
    {
        const int   s  = tap >> 1;
        float c  = x1 + ((float)wbin + 0.25f + 0.5f * (float)s) * bw;
        float v  = (c > -1.0f && c < (float)W_) ? 1.0f : 0.0f;
        float cc = fminf(fmaxf(c, 0.0f), (float)(W_ - 1));
        int   lo = (int)cc;
        int   hi = (lo < W_ - 1) ? lo + 1 : lo;
        float f  = cc - (float)lo;
        xoff = (tap & 1) ? hi : lo;
        xw   = ((tap & 1) ? f : (1.0f - f)) * v;
        if (!active) xw = 0.0f;
    }

    const int c0 = cg * CG;
    const float* pbase = feat + ((size_t)b * C_ + c0) * (size_t)DHW_ + xoff;
    float* obase0 = out + ((size_t)(r * C_ + c0)) * (size_t)NBINS + wbin;

    // ---- Interleaved combo loop: k = wi, wi+5, ... ; k = d*7 + h ----
    for (int k = wi; k < NCOMBO; k += NWARP) {
        const int d = k / OUTH;
        const int h = k % OUTH;

        // 4 y taps (depend on h)
        int   yoff[4];
        float yw[4];
#pragma unroll
        for (int s = 0; s < SN_; s++) {
            float c  = y1 + ((float)h + 0.25f + 0.5f * (float)s) * bh;
            float v  = (c > -1.0f && c < (float)H_) ? 1.0f : 0.0f;
            float cc = fminf(fmaxf(c, 0.0f), (float)(H_ - 1));
            int   lo = (int)cc;
            int   hi = (lo < H_ - 1) ? lo + 1 : lo;
            float f  = cc - (float)lo;
            yoff[2*s]   = lo * W_;  yw[2*s]   = (1.0f - f) * v;
            yoff[2*s+1] = hi * W_;  yw[2*s+1] = f * v;
        }

        // 4 z taps (depend on d)
        int   zoff[4];
        float zw[4];
#pragma unroll
        for (int s = 0; s < SN_; s++) {
            float c  = z1 + ((float)d + 0.25f + 0.5f * (float)s) * bd;
            float v  = (c > -1.0f && c < (float)D_) ? 1.0f : 0.0f;
            float cc = fminf(fmaxf(c, 0.0f), (float)(D_ - 1));
            int   lo = (int)cc;
            int   hi = (lo < D_ - 1) ? lo + 1 : lo;
            float f  = cc - (float)lo;
            zoff[2*s]   = lo * HW_;  zw[2*s]   = (1.0f - f) * v;
            zoff[2*s+1] = hi * HW_;  zw[2*s+1] = f * v;
        }

        // 16 row offsets + scalar weights (uniform across warp)
        int   rowoff[16];
        float wzy[16];
#pragma unroll
        for (int zt = 0; zt < 4; zt++)
#pragma unroll
            for (int yt = 0; yt < 4; yt++) {
                rowoff[zt * 4 + yt] = zoff[zt] + yoff[yt];
                wzy[zt * 4 + yt]    = zw[zt] * yw[yt];
            }

        float* od = obase0 + (size_t)d * (OUTH * OUTH) + h * OUTH;

        // ---- Channel loop, 2 channels at a time (32 independent LDGs) ----
        for (int ci = 0; ci < CG; ci += 2) {
            const float* pA = pbase + (size_t)ci * DHW_;
            const float* pB = pA + DHW_;

            float vA[16], vB[16];
#pragma unroll
            for (int i = 0; i < 16; i++) {
                vA[i] = __ldg(pA + rowoff[i]);
                vB[i] = __ldg(pB + rowoff[i]);
            }

            // two partial chains each to shorten the FMA dependency
            float a0 = 0.f, a1 = 0.f, b0 = 0.f, b1 = 0.f;
#pragma unroll
            for (int i = 0; i < 16; i += 2) {
                a0 = fmaf(wzy[i],     vA[i],     a0);
                a1 = fmaf(wzy[i + 1], vA[i + 1], a1);
                b0 = fmaf(wzy[i],     vB[i],     b0);
                b1 = fmaf(wzy[i + 1], vB[i + 1], b1);
            }
            float accA = (a0 + a1) * xw;
            float accB = (b0 + b1) * xw;

            // reduce across the 4 x-taps (lanes 4w..4w+3)
            accA += __shfl_xor_sync(0xFFFFFFFFu, accA, 1);
            accA += __shfl_xor_sync(0xFFFFFFFFu, accA, 2);
            accB += __shfl_xor_sync(0xFFFFFFFFu, accB, 1);
            accB += __shfl_xor_sync(0xFFFFFFFFu, accB, 2);

            if (active && tap == 0) {
                od[(size_t)ci * NBINS]       = accA * 0.125f;  // mean over 8 samples
                od[(size_t)(ci + 1) * NBINS] = accB * 0.125f;
            }
        }
    }
}

extern "C" void kernel_launch(void* const* d_in, const int* in_sizes, int n_in,
                              void* d_out, int out_size)
{
    const float* feat = (const float*)d_in[0];
    const float* rois = (const float*)d_in[1];
    float* out = (float*)d_out;

    const int R = in_sizes[1] / 7;   // 256

    dim3 grid(R, C_ / CG, 1);        // 256 x 8 = 2048 blocks
    dim3 block(TPB, 1, 1);           // 160 threads (5 warps)
    roialign3d_kernel<<<grid, block>>>(feat, rois, out, R);
}